// round 1
// baseline (speedup 1.0000x reference)
#include <cuda_runtime.h>
#include <math.h>

#define D 128
#define NHEADS 8
#define NMAX 50000

// ---- scratch (no allocations allowed; device globals) ----
__device__ float g_Q[NMAX * D];
__device__ float g_K[NMAX * D];
__device__ float g_V[NMAX * D];
__device__ float g_wV[NMAX * D];
__device__ float g_z[NMAX * NHEADS];
__device__ float g_h[NMAX * D];
__device__ float g_g[NMAX * D];

// ============================================================
// SGEMM: C[M,128] = A[M,128] @ W[128,128] + bias
// MODE 0: plain.  MODE 1: C = R + relu(A@W + bias)
// BM=BN=128, BK=32, 256 threads, 8x8 microtile per thread.
// ============================================================
template <int MODE>
__device__ __forceinline__ void gemm_body(
    const float* __restrict__ A, const float* __restrict__ W,
    const float* __restrict__ bias, float* __restrict__ C,
    const float* __restrict__ R, int M)
{
    __shared__ float As[32][129];   // [k][m], pad 129 -> conflict-free transposed stores
    __shared__ float Bs[32][128];   // [k][n]

    const int tid  = threadIdx.x;          // 0..255
    const int tx   = tid & 15;             // 0..15 -> n
    const int ty   = tid >> 4;             // 0..15 -> m
    const int row0 = blockIdx.x * 128;

    float acc[8][8];
#pragma unroll
    for (int i = 0; i < 8; i++)
#pragma unroll
        for (int j = 0; j < 8; j++) acc[i][j] = 0.0f;

    const int arow = tid >> 3;            // 0..31
    const int acol = (tid & 7) << 2;      // 0,4,...,28
    const int brow = tid >> 5;            // 0..7
    const int bcol = (tid & 31) << 2;     // 0..124

    for (int kk = 0; kk < 128; kk += 32) {
        __syncthreads();
        // A tile (transposed into As[k][m])
#pragma unroll
        for (int p = 0; p < 4; p++) {
            int r = row0 + arow + p * 32;
            float4 v = make_float4(0.f, 0.f, 0.f, 0.f);
            if (r < M) v = *(const float4*)(A + (size_t)r * 128 + kk + acol);
            int m = arow + p * 32;
            As[acol + 0][m] = v.x;
            As[acol + 1][m] = v.y;
            As[acol + 2][m] = v.z;
            As[acol + 3][m] = v.w;
        }
        // W tile
#pragma unroll
        for (int p = 0; p < 4; p++) {
            int r = kk + brow + p * 8;
            *(float4*)&Bs[brow + p * 8][bcol] =
                *(const float4*)(W + (size_t)r * 128 + bcol);
        }
        __syncthreads();

#pragma unroll
        for (int k = 0; k < 32; k++) {
            float a[8];
#pragma unroll
            for (int i = 0; i < 8; i++) a[i] = As[k][ty * 8 + i];
            float4 b0 = *(float4*)&Bs[k][tx * 8];
            float4 b1 = *(float4*)&Bs[k][tx * 8 + 4];
            float b[8] = {b0.x, b0.y, b0.z, b0.w, b1.x, b1.y, b1.z, b1.w};
#pragma unroll
            for (int i = 0; i < 8; i++)
#pragma unroll
                for (int j = 0; j < 8; j++)
                    acc[i][j] = fmaf(a[i], b[j], acc[i][j]);
        }
    }

    // epilogue
    const int c0 = tx * 8;
    float4 bb0 = *(const float4*)(bias + c0);
    float4 bb1 = *(const float4*)(bias + c0 + 4);
    float bb[8] = {bb0.x, bb0.y, bb0.z, bb0.w, bb1.x, bb1.y, bb1.z, bb1.w};
#pragma unroll
    for (int i = 0; i < 8; i++) {
        int r = row0 + ty * 8 + i;
        if (r >= M) continue;
        float v[8];
#pragma unroll
        for (int j = 0; j < 8; j++) {
            float val = acc[i][j] + bb[j];
            if (MODE == 1) {
                val = R[(size_t)r * 128 + c0 + j] + fmaxf(val, 0.0f);
            }
            v[j] = val;
        }
        *(float4*)(C + (size_t)r * 128 + c0)     = make_float4(v[0], v[1], v[2], v[3]);
        *(float4*)(C + (size_t)r * 128 + c0 + 4) = make_float4(v[4], v[5], v[6], v[7]);
    }
}

__global__ __launch_bounds__(256) void qkv_kernel(
    const float* __restrict__ x,
    const float* __restrict__ Wq, const float* __restrict__ bq,
    const float* __restrict__ Wk, const float* __restrict__ bk,
    const float* __restrict__ Wv, const float* __restrict__ bv, int M)
{
    if (blockIdx.y == 0)      gemm_body<0>(x, Wq, bq, g_Q, nullptr, M);
    else if (blockIdx.y == 1) gemm_body<0>(x, Wk, bk, g_K, nullptr, M);
    else                      gemm_body<0>(x, Wv, bv, g_V, nullptr, M);
}

__global__ __launch_bounds__(256) void out_gemm_kernel(
    const float* __restrict__ Wo, const float* __restrict__ bo,
    float* __restrict__ out, int M)
{
    gemm_body<1>(g_g, Wo, bo, out, g_h, M);
}

// ============================================================
// zero wV / z accumulators
// ============================================================
__global__ void zero_kernel(int n_wv, int n_z)
{
    int i = blockIdx.x * blockDim.x + threadIdx.x;
    int stride = gridDim.x * blockDim.x;
    for (int j = i; j < n_wv; j += stride) g_wV[j] = 0.0f;
    for (int j = i; j < n_z;  j += stride) g_z[j]  = 0.0f;
}

// ============================================================
// edge kernel: one warp per edge.
// score[e,h] = exp(clip(dot(K[src],Q[dst])_h / 4, -5, 5))
// wV[dst] += V[src]*score ; z[dst] += score
// ============================================================
__global__ __launch_bounds__(256) void edge_kernel(
    const int* __restrict__ src, const int* __restrict__ dst, int E)
{
    int w = (int)((blockIdx.x * blockDim.x + threadIdx.x) >> 5);
    int lane = threadIdx.x & 31;
    if (w >= E) return;
    int s = src[w];
    int d = dst[w];

    const float4* Q4 = (const float4*)g_Q;
    const float4* K4 = (const float4*)g_K;
    const float4* V4 = (const float4*)g_V;

    float4 q = Q4[(size_t)d * 32 + lane];
    float4 k = K4[(size_t)s * 32 + lane];
    float4 v = V4[(size_t)s * 32 + lane];

    float p = q.x * k.x + q.y * k.y + q.z * k.z + q.w * k.w;
    // reduce within each group of 4 lanes (one head = 16 floats)
    p += __shfl_xor_sync(0xffffffffu, p, 1);
    p += __shfl_xor_sync(0xffffffffu, p, 2);
    float sc = p * 0.25f;                 // 1/sqrt(16)
    sc = fminf(fmaxf(sc, -5.0f), 5.0f);
    sc = expf(sc);

    if ((lane & 3) == 0) {
        float* zp = &g_z[(size_t)d * NHEADS + (lane >> 2)];
        asm volatile("red.global.add.f32 [%0], %1;" :: "l"(zp), "f"(sc) : "memory");
    }

    float* wp = &g_wV[(size_t)d * 128 + lane * 4];
    asm volatile("red.global.add.v4.f32 [%0], {%1,%2,%3,%4};"
                 :: "l"(wp), "f"(v.x * sc), "f"(v.y * sc), "f"(v.z * sc), "f"(v.w * sc)
                 : "memory");
}

// ============================================================
// attn normalize + residual + LN1 -> h ; LN2(h) -> g
// one warp per row
// ============================================================
__global__ __launch_bounds__(256) void attn_ln_kernel(
    const float* __restrict__ x,
    const float* __restrict__ gamma1, const float* __restrict__ beta1,
    const float* __restrict__ gamma2, const float* __restrict__ beta2, int M)
{
    int w = (int)((blockIdx.x * blockDim.x + threadIdx.x) >> 5);
    int lane = threadIdx.x & 31;
    if (w >= M) return;

    const float4* x4  = (const float4*)x;
    const float4* wv4 = (const float4*)g_wV;

    float4 xv = x4[(size_t)w * 32 + lane];
    float4 wv = wv4[(size_t)w * 32 + lane];
    float inv = 1.0f / (g_z[(size_t)w * NHEADS + (lane >> 2)] + 1e-3f);

    float4 y;
    y.x = xv.x + wv.x * inv;
    y.y = xv.y + wv.y * inv;
    y.z = xv.z + wv.z * inv;
    y.w = xv.w + wv.w * inv;

    float s  = y.x + y.y + y.z + y.w;
    float sq = y.x * y.x + y.y * y.y + y.z * y.z + y.w * y.w;
#pragma unroll
    for (int o = 16; o > 0; o >>= 1) {
        s  += __shfl_xor_sync(0xffffffffu, s, o);
        sq += __shfl_xor_sync(0xffffffffu, sq, o);
    }
    float mu   = s * (1.0f / 128.0f);
    float var  = sq * (1.0f / 128.0f) - mu * mu;
    float rstd = rsqrtf(var + 1e-5f);

    float4 g1 = ((const float4*)gamma1)[lane];
    float4 b1 = ((const float4*)beta1)[lane];
    float4 hv;
    hv.x = (y.x - mu) * rstd * g1.x + b1.x;
    hv.y = (y.y - mu) * rstd * g1.y + b1.y;
    hv.z = (y.z - mu) * rstd * g1.z + b1.z;
    hv.w = (y.w - mu) * rstd * g1.w + b1.w;
    ((float4*)g_h)[(size_t)w * 32 + lane] = hv;

    // second LN over h
    float s2  = hv.x + hv.y + hv.z + hv.w;
    float sq2 = hv.x * hv.x + hv.y * hv.y + hv.z * hv.z + hv.w * hv.w;
#pragma unroll
    for (int o = 16; o > 0; o >>= 1) {
        s2  += __shfl_xor_sync(0xffffffffu, s2, o);
        sq2 += __shfl_xor_sync(0xffffffffu, sq2, o);
    }
    float mu2   = s2 * (1.0f / 128.0f);
    float var2  = sq2 * (1.0f / 128.0f) - mu2 * mu2;
    float rstd2 = rsqrtf(var2 + 1e-5f);

    float4 g2 = ((const float4*)gamma2)[lane];
    float4 b2 = ((const float4*)beta2)[lane];
    float4 gv;
    gv.x = (hv.x - mu2) * rstd2 * g2.x + b2.x;
    gv.y = (hv.y - mu2) * rstd2 * g2.y + b2.y;
    gv.z = (hv.z - mu2) * rstd2 * g2.z + b2.z;
    gv.w = (hv.w - mu2) * rstd2 * g2.w + b2.w;
    ((float4*)g_g)[(size_t)w * 32 + lane] = gv;
}

// ============================================================
extern "C" void kernel_launch(void* const* d_in, const int* in_sizes, int n_in,
                              void* d_out, int out_size)
{
    const float* x      = (const float*)d_in[0];
    const int*   src    = (const int*)  d_in[1];
    const int*   dst    = (const int*)  d_in[2];
    const float* Wq     = (const float*)d_in[3];
    const float* bq     = (const float*)d_in[4];
    const float* Wk     = (const float*)d_in[5];
    const float* bk     = (const float*)d_in[6];
    const float* Wv     = (const float*)d_in[7];
    const float* bv     = (const float*)d_in[8];
    const float* Wo     = (const float*)d_in[9];
    const float* bo     = (const float*)d_in[10];
    const float* gamma1 = (const float*)d_in[11];
    const float* beta1  = (const float*)d_in[12];
    const float* gamma2 = (const float*)d_in[13];
    const float* beta2  = (const float*)d_in[14];
    float* out = (float*)d_out;

    int M = in_sizes[0] / 128;
    int E = in_sizes[1];

    zero_kernel<<<512, 256>>>(M * 128, M * NHEADS);

    dim3 gq((M + 127) / 128, 3);
    qkv_kernel<<<gq, 256>>>(x, Wq, bq, Wk, bk, Wv, bv, M);

    int edge_blocks = (E + 7) / 8;  // 8 warps/block
    edge_kernel<<<edge_blocks, 256>>>(src, dst, E);

    attn_ln_kernel<<<(M * 32 + 255) / 256, 256>>>(x, gamma1, beta1, gamma2, beta2, M);

    out_gemm_kernel<<<(M + 127) / 128, 256>>>(Wo, bo, out, M);
}